// round 13
// baseline (speedup 1.0000x reference)
#include <cuda_runtime.h>

#define D      512
#define W      5
#define TPB    256
#define MAX_TIME_ROWS 512

// Precomputed fp32 (sin, cos) interleaved: g_trig[row*D + dim] = (s, c). 1.5MB, L2-resident.
__device__ float2 g_trig[MAX_TIME_ROWS * D];

__global__ void trig_kernel(const float* __restrict__ tt, int n) {
    int i = blockIdx.x * blockDim.x + threadIdx.x;
    if (i < n) {
        float s, c;
        sincosf(tt[i], &s, &c);
        g_trig[i] = make_float2(s, c);
    }
}

// TPB=256: each thread owns dims {2*tid, 2*tid+1}. Halves per-thread regs/FMA vs 128-thread
// version -> ~64 regs -> 4 CTAs/SM (50% occ) to hide the ~800cy entity-gather latency.
__global__ __launch_bounds__(TPB) void contxe_kernel(
    const int*   __restrict__ h_i,
    const int*   __restrict__ t_i,
    const int*   __restrict__ r_i,
    const int*   __restrict__ d_i,
    const float* __restrict__ eEr,
    const float* __restrict__ eEi,
    const float* __restrict__ eRr,
    const float* __restrict__ eRi,
    float*       __restrict__ out,
    int n_day)
{
    const int b    = blockIdx.x;
    const int tid  = threadIdx.x;
    const int lane = tid & 31;
    const int warp = tid >> 5;

    __shared__ float red[8][20];
    __shared__ float sh_w[20];
    __shared__ float partial[8];

    const int h = h_i[b];
    const int t = t_i[b];
    const int r = r_i[b];
    const int d = d_i[b];

    // ---- Embedding gathers FIRST (DRAM latency — in flight at cycle 0) ----
    const float2 hr2 = ((const float2*)(eEr + (size_t)h * D))[tid];
    const float2 hi2 = ((const float2*)(eEi + (size_t)h * D))[tid];
    const float2 tr2 = ((const float2*)(eEr + (size_t)t * D))[tid];
    const float2 ti2 = ((const float2*)(eEi + (size_t)t * D))[tid];
    const float2 rr2 = ((const float2*)(eRr + (size_t)r * D))[tid];
    const float2 ri2 = ((const float2*)(eRi + (size_t)r * D))[tid];

    // ---- Trig: one LDG.128 per window slot = 2 fp32 (s,c) pairs (L2 hits) ----
    float4 T[W];
    const float4* gt = (const float4*)g_trig;   // row stride = D/2 float4
    #pragma unroll
    for (int w = 0; w < W; w++) {
        int row = d - (W - 1 - w);
        if (row < 0) row = n_day;
        T[w] = gt[row * (D / 2) + tid];
    }

    const float* hrp = (const float*)&hr2;
    const float* hip = (const float*)&hi2;
    const float* trp = (const float*)&tr2;
    const float* tip = (const float*)&ti2;
    const float* rrp = (const float*)&rr2;
    const float* rip = (const float*)&ri2;

    // ---- Pass 1: 20 attention-score partial dots (2 dims per thread) ----
    float acc[20];
    #pragma unroll
    for (int j = 0; j < 20; j++) acc[j] = 0.0f;

    #pragma unroll
    for (int w = 0; w < W; w++) {
        const float sv[2] = { T[w].x, T[w].z };
        const float cv[2] = { T[w].y, T[w].w };
        #pragma unroll
        for (int k = 0; k < 2; k++) {
            const float s = sv[k], c = cv[k];
            const float hre = fmaf(hrp[k], c, -hip[k] * s);
            const float him = fmaf(hrp[k], s,  hip[k] * c);
            const float tre = fmaf(trp[k], c, -tip[k] * s);
            const float tim = fmaf(trp[k], s,  tip[k] * c);
            acc[0 * W + w] = fmaf(rrp[k], hre, acc[0 * W + w]);
            acc[1 * W + w] = fmaf(rip[k], him, acc[1 * W + w]);
            acc[2 * W + w] = fmaf(rrp[k], tre, acc[2 * W + w]);
            acc[3 * W + w] = fmaf(rip[k], tim, acc[3 * W + w]);
        }
    }

    // ---- Warp butterfly reduce each of the 20 accumulators ----
    #pragma unroll
    for (int j = 0; j < 20; j++) {
        float v = acc[j];
        v += __shfl_xor_sync(0xffffffffu, v, 16);
        v += __shfl_xor_sync(0xffffffffu, v, 8);
        v += __shfl_xor_sync(0xffffffffu, v, 4);
        v += __shfl_xor_sync(0xffffffffu, v, 2);
        v += __shfl_xor_sync(0xffffffffu, v, 1);
        if (lane == 0) red[warp][j] = v;
    }
    __syncthreads();

    // ---- 4 threads each do one 5-way softmax (summing 8 warps) ----
    if (tid < 4) {
        float sc[W];
        float m = -1e30f;
        #pragma unroll
        for (int w = 0; w < W; w++) {
            float v = 0.0f;
            #pragma unroll
            for (int q = 0; q < 8; q++) v += red[q][tid * W + w];
            sc[w] = v;
            m = fmaxf(m, v);
        }
        float sum = 0.0f;
        #pragma unroll
        for (int w = 0; w < W; w++) {
            sc[w] = expf(sc[w] - m);
            sum += sc[w];
        }
        float inv = 1.0f / sum;
        #pragma unroll
        for (int w = 0; w < W; w++) sh_w[tid * W + w] = sc[w] * inv;
    }
    __syncthreads();

    // ---- Pass 2: weighted sums (trig reused from registers) ----
    float yre[2] = {0, 0};
    float yim[2] = {0, 0};
    float zre[2] = {0, 0};
    float zim[2] = {0, 0};

    #pragma unroll
    for (int w = 0; w < W; w++) {
        const float wa_r = sh_w[0 * W + w];   // LDS broadcasts
        const float wa_i = sh_w[1 * W + w];
        const float wb_r = sh_w[2 * W + w];
        const float wb_i = sh_w[3 * W + w];
        const float sv[2] = { T[w].x, T[w].z };
        const float cv[2] = { T[w].y, T[w].w };
        #pragma unroll
        for (int k = 0; k < 2; k++) {
            const float s = sv[k], c = cv[k];
            const float hre = fmaf(hrp[k], c, -hip[k] * s);
            const float him = fmaf(hrp[k], s,  hip[k] * c);
            const float tre = fmaf(trp[k], c, -tip[k] * s);
            const float tim = fmaf(trp[k], s,  tip[k] * c);
            yre[k] = fmaf(wa_r, hre, yre[k]);
            yim[k] = fmaf(wa_i, him, yim[k]);
            zre[k] = fmaf(wb_r, tre, zre[k]);
            zim[k] = fmaf(wb_i, tim, zim[k]);
        }
    }

    float local = 0.0f;
    #pragma unroll
    for (int k = 0; k < 2; k++) {
        local += fabsf(yre[k] + rrp[k] - zre[k]);
        local += fabsf(yim[k] + rip[k] + zim[k]);
    }

    local += __shfl_xor_sync(0xffffffffu, local, 16);
    local += __shfl_xor_sync(0xffffffffu, local, 8);
    local += __shfl_xor_sync(0xffffffffu, local, 4);
    local += __shfl_xor_sync(0xffffffffu, local, 2);
    local += __shfl_xor_sync(0xffffffffu, local, 1);
    if (lane == 0) partial[warp] = local;
    __syncthreads();

    if (tid == 0) {
        float s = 0.0f;
        #pragma unroll
        for (int q = 0; q < 8; q++) s += partial[q];
        out[b] = s;
    }
}

extern "C" void kernel_launch(void* const* d_in, const int* in_sizes, int n_in,
                              void* d_out, int out_size) {
    const int*   h_i = (const int*)  d_in[0];
    const int*   t_i = (const int*)  d_in[1];
    const int*   r_i = (const int*)  d_in[2];
    const int*   d_i = (const int*)  d_in[3];
    const float* eEr = (const float*)d_in[4];
    const float* eEi = (const float*)d_in[5];
    const float* eRr = (const float*)d_in[6];
    const float* eRi = (const float*)d_in[7];
    const float* tt  = (const float*)d_in[8];

    const int B          = in_sizes[0];
    const int time_elems = in_sizes[8];
    const int time_rows  = time_elems / D;
    const int n_day      = time_rows - 2;

    trig_kernel<<<(time_elems + 255) / 256, 256>>>(tt, time_elems);
    contxe_kernel<<<B, TPB>>>(h_i, t_i, r_i, d_i, eEr, eEi, eRr, eRi,
                              (float*)d_out, n_day);
}

// round 14
// speedup vs baseline: 1.5481x; 1.5481x over previous
#include <cuda_runtime.h>

#define D      512
#define W      5
#define TPB    128
#define MAX_TIME_ROWS 512

// Precomputed fp32 sin/cos of the time table (row-major [rows][D]). 1.5MB, L2-resident.
__device__ float g_sin[MAX_TIME_ROWS * D];
__device__ float g_cos[MAX_TIME_ROWS * D];

__global__ void trig_kernel(const float* __restrict__ tt, int n) {
    int i = blockIdx.x * blockDim.x + threadIdx.x;
    if (i < n) {
        float s, c;
        sincosf(tt[i], &s, &c);
        g_sin[i] = s;
        g_cos[i] = c;
    }
}

// Rotation form in both passes, trig loaded per window slot (transient 8 regs,
// pass 2 re-reads the same lines from L1). Target <=64 regs -> 8 CTAs/SM.
__global__ __launch_bounds__(TPB, 8) void contxe_kernel(
    const int*   __restrict__ h_i,
    const int*   __restrict__ t_i,
    const int*   __restrict__ r_i,
    const int*   __restrict__ d_i,
    const float* __restrict__ eEr,
    const float* __restrict__ eEi,
    const float* __restrict__ eRr,
    const float* __restrict__ eRi,
    float*       __restrict__ out,
    int n_day)
{
    const int b    = blockIdx.x;
    const int tid  = threadIdx.x;
    const int lane = tid & 31;
    const int warp = tid >> 5;

    __shared__ float acc_s[TPB * 20];   // 10 KB
    __shared__ float sums[20];
    __shared__ float sh_w[20];
    __shared__ float partial[4];

    const int h = h_i[b];
    const int t = t_i[b];
    const int r = r_i[b];
    const int d = d_i[b];

    // ---- Embedding gathers FIRST (DRAM latency — in flight at cycle 0) ----
    const float4 hr4 = ((const float4*)(eEr + (size_t)h * D))[tid];
    const float4 hi4 = ((const float4*)(eEi + (size_t)h * D))[tid];
    const float4 tr4 = ((const float4*)(eEr + (size_t)t * D))[tid];
    const float4 ti4 = ((const float4*)(eEi + (size_t)t * D))[tid];
    const float4 rr4 = ((const float4*)(eRr + (size_t)r * D))[tid];
    const float4 ri4 = ((const float4*)(eRi + (size_t)r * D))[tid];

    // Window row indices (5 int regs, reused by both passes).
    int rows[W];
    #pragma unroll
    for (int w = 0; w < W; w++) {
        int row = d - (W - 1 - w);
        rows[w] = (row < 0) ? n_day : row;
    }

    const float* hrp = (const float*)&hr4;
    const float* hip = (const float*)&hi4;
    const float* trp = (const float*)&tr4;
    const float* tip = (const float*)&ti4;
    const float* rrp = (const float*)&rr4;
    const float* rip = (const float*)&ri4;

    const float4* sT = (const float4*)g_sin;
    const float4* cT = (const float4*)g_cos;

    // ---- Pass 1: 20 attention-score partial dots (rotation form, trig transient) ----
    float acc[20];
    #pragma unroll
    for (int j = 0; j < 20; j++) acc[j] = 0.0f;

    #pragma unroll
    for (int w = 0; w < W; w++) {
        const float4 s4 = sT[rows[w] * (D / 4) + tid];
        const float4 c4 = cT[rows[w] * (D / 4) + tid];
        const float* sp = (const float*)&s4;
        const float* cp = (const float*)&c4;
        #pragma unroll
        for (int k = 0; k < 4; k++) {
            const float s = sp[k], c = cp[k];
            const float hre = fmaf(hrp[k], c, -hip[k] * s);
            const float him = fmaf(hrp[k], s,  hip[k] * c);
            const float tre = fmaf(trp[k], c, -tip[k] * s);
            const float tim = fmaf(trp[k], s,  tip[k] * c);
            acc[0 * W + w] = fmaf(rrp[k], hre, acc[0 * W + w]);
            acc[1 * W + w] = fmaf(rip[k], him, acc[1 * W + w]);
            acc[2 * W + w] = fmaf(rrp[k], tre, acc[2 * W + w]);
            acc[3 * W + w] = fmaf(rip[k], tim, acc[3 * W + w]);
        }
    }

    // ---- Cross-thread reduction: STS.128 dump + 20-thread column sums (champion path) ----
    {
        float4* rowp = (float4*)(acc_s + tid * 20);
        #pragma unroll
        for (int j = 0; j < 5; j++)
            rowp[j] = make_float4(acc[4 * j], acc[4 * j + 1], acc[4 * j + 2], acc[4 * j + 3]);
    }
    __syncthreads();

    if (tid < 20) {
        float v0 = 0.f, v1 = 0.f, v2 = 0.f, v3 = 0.f;
        #pragma unroll
        for (int i = 0; i < TPB; i += 4) {
            v0 += acc_s[(i + 0) * 20 + tid];
            v1 += acc_s[(i + 1) * 20 + tid];
            v2 += acc_s[(i + 2) * 20 + tid];
            v3 += acc_s[(i + 3) * 20 + tid];
        }
        sums[tid] = (v0 + v1) + (v2 + v3);
    }
    __syncthreads();

    // ---- 4 threads each do one 5-way softmax ----
    if (tid < 4) {
        float sc[W];
        float m = -1e30f;
        #pragma unroll
        for (int w = 0; w < W; w++) {
            sc[w] = sums[tid * W + w];
            m = fmaxf(m, sc[w]);
        }
        float sum = 0.0f;
        #pragma unroll
        for (int w = 0; w < W; w++) {
            sc[w] = expf(sc[w] - m);
            sum += sc[w];
        }
        float inv = 1.0f / sum;
        #pragma unroll
        for (int w = 0; w < W; w++) sh_w[tid * W + w] = sc[w] * inv;
    }
    __syncthreads();

    // ---- Pass 2: weighted sums (rotation form, 16 accums, trig re-read from L1) ----
    float yre[4] = {0, 0, 0, 0};
    float yim[4] = {0, 0, 0, 0};
    float zre[4] = {0, 0, 0, 0};
    float zim[4] = {0, 0, 0, 0};

    #pragma unroll
    for (int w = 0; w < W; w++) {
        const float wa_r = sh_w[0 * W + w];   // LDS broadcasts
        const float wa_i = sh_w[1 * W + w];
        const float wb_r = sh_w[2 * W + w];
        const float wb_i = sh_w[3 * W + w];
        const float4 s4 = sT[rows[w] * (D / 4) + tid];   // L1 hit (same line as pass 1)
        const float4 c4 = cT[rows[w] * (D / 4) + tid];
        const float* sp = (const float*)&s4;
        const float* cp = (const float*)&c4;
        #pragma unroll
        for (int k = 0; k < 4; k++) {
            const float s = sp[k], c = cp[k];
            const float hre = fmaf(hrp[k], c, -hip[k] * s);
            const float him = fmaf(hrp[k], s,  hip[k] * c);
            const float tre = fmaf(trp[k], c, -tip[k] * s);
            const float tim = fmaf(trp[k], s,  tip[k] * c);
            yre[k] = fmaf(wa_r, hre, yre[k]);
            yim[k] = fmaf(wa_i, him, yim[k]);
            zre[k] = fmaf(wb_r, tre, zre[k]);
            zim[k] = fmaf(wb_i, tim, zim[k]);
        }
    }

    float local = 0.0f;
    #pragma unroll
    for (int k = 0; k < 4; k++) {
        local += fabsf(yre[k] + rrp[k] - zre[k]);
        local += fabsf(yim[k] + rip[k] + zim[k]);
    }

    local += __shfl_xor_sync(0xffffffffu, local, 16);
    local += __shfl_xor_sync(0xffffffffu, local, 8);
    local += __shfl_xor_sync(0xffffffffu, local, 4);
    local += __shfl_xor_sync(0xffffffffu, local, 2);
    local += __shfl_xor_sync(0xffffffffu, local, 1);
    if (lane == 0) partial[warp] = local;
    __syncthreads();

    if (tid == 0) {
        out[b] = (partial[0] + partial[1]) + (partial[2] + partial[3]);
    }
}

extern "C" void kernel_launch(void* const* d_in, const int* in_sizes, int n_in,
                              void* d_out, int out_size) {
    const int*   h_i = (const int*)  d_in[0];
    const int*   t_i = (const int*)  d_in[1];
    const int*   r_i = (const int*)  d_in[2];
    const int*   d_i = (const int*)  d_in[3];
    const float* eEr = (const float*)d_in[4];
    const float* eEi = (const float*)d_in[5];
    const float* eRr = (const float*)d_in[6];
    const float* eRi = (const float*)d_in[7];
    const float* tt  = (const float*)d_in[8];

    const int B          = in_sizes[0];
    const int time_elems = in_sizes[8];
    const int time_rows  = time_elems / D;
    const int n_day      = time_rows - 2;

    trig_kernel<<<(time_elems + 255) / 256, 256>>>(tt, time_elems);
    contxe_kernel<<<B, TPB>>>(h_i, t_i, r_i, d_i, eEr, eEi, eRr, eRi,
                              (float*)d_out, n_day);
}

// round 15
// speedup vs baseline: 1.6713x; 1.0796x over previous
#include <cuda_runtime.h>
#include <cuda_fp16.h>

#define D      512
#define W      5
#define TPB    128
#define MAX_TIME_ROWS 512

// Precomputed (sin, cos) of the time table as fp16 pairs: g_trig[row*D + dim] = half2(s, c).
// 367*512*4B = 750 KB — L2-resident; 2KB per row -> 10KB per CTA window working set.
__device__ __half2 g_trig[MAX_TIME_ROWS * D];

__global__ void trig_kernel(const float* __restrict__ tt, int n) {
    int i = blockIdx.x * blockDim.x + threadIdx.x;
    if (i < n) {
        float s, c;
        sincosf(tt[i], &s, &c);
        g_trig[i] = __floats2half2_rn(s, c);
    }
}

// R14 structure (64 regs, 8 CTAs/SM) with fp16 transient trig: one LDG.128 per
// window slot per pass (halves trig L2 traffic vs fp32 transient; pass 2 hits L1).
__global__ __launch_bounds__(TPB, 8) void contxe_kernel(
    const int*   __restrict__ h_i,
    const int*   __restrict__ t_i,
    const int*   __restrict__ r_i,
    const int*   __restrict__ d_i,
    const float* __restrict__ eEr,
    const float* __restrict__ eEi,
    const float* __restrict__ eRr,
    const float* __restrict__ eRi,
    float*       __restrict__ out,
    int n_day)
{
    const int b    = blockIdx.x;
    const int tid  = threadIdx.x;
    const int lane = tid & 31;
    const int warp = tid >> 5;

    __shared__ float acc_s[TPB * 20];   // 10 KB
    __shared__ float sums[20];
    __shared__ float sh_w[20];
    __shared__ float partial[4];

    const int h = h_i[b];
    const int t = t_i[b];
    const int r = r_i[b];
    const int d = d_i[b];

    // ---- Embedding gathers FIRST (DRAM latency — in flight at cycle 0) ----
    const float4 hr4 = ((const float4*)(eEr + (size_t)h * D))[tid];
    const float4 hi4 = ((const float4*)(eEi + (size_t)h * D))[tid];
    const float4 tr4 = ((const float4*)(eEr + (size_t)t * D))[tid];
    const float4 ti4 = ((const float4*)(eEi + (size_t)t * D))[tid];
    const float4 rr4 = ((const float4*)(eRr + (size_t)r * D))[tid];
    const float4 ri4 = ((const float4*)(eRi + (size_t)r * D))[tid];

    // Window row indices (5 int regs, reused by both passes).
    int rows[W];
    #pragma unroll
    for (int w = 0; w < W; w++) {
        int row = d - (W - 1 - w);
        rows[w] = (row < 0) ? n_day : row;
    }

    const float* hrp = (const float*)&hr4;
    const float* hip = (const float*)&hi4;
    const float* trp = (const float*)&tr4;
    const float* tip = (const float*)&ti4;
    const float* rrp = (const float*)&rr4;
    const float* rip = (const float*)&ri4;

    const uint4* gt = (const uint4*)g_trig;   // 4 half2 (s,c) pairs per uint4; D/4 per row

    // ---- Pass 1: 20 attention-score partial dots (rotation form, trig transient) ----
    float acc[20];
    #pragma unroll
    for (int j = 0; j < 20; j++) acc[j] = 0.0f;

    #pragma unroll
    for (int w = 0; w < W; w++) {
        const uint4 tv = gt[rows[w] * (D / 4) + tid];
        const __half2* tp = (const __half2*)&tv;
        #pragma unroll
        for (int k = 0; k < 4; k++) {
            const float2 sc = __half22float2(tp[k]);
            const float s = sc.x, c = sc.y;
            const float hre = fmaf(hrp[k], c, -hip[k] * s);
            const float him = fmaf(hrp[k], s,  hip[k] * c);
            const float tre = fmaf(trp[k], c, -tip[k] * s);
            const float tim = fmaf(trp[k], s,  tip[k] * c);
            acc[0 * W + w] = fmaf(rrp[k], hre, acc[0 * W + w]);
            acc[1 * W + w] = fmaf(rip[k], him, acc[1 * W + w]);
            acc[2 * W + w] = fmaf(rrp[k], tre, acc[2 * W + w]);
            acc[3 * W + w] = fmaf(rip[k], tim, acc[3 * W + w]);
        }
    }

    // ---- Cross-thread reduction: STS.128 dump + 20-thread column sums ----
    {
        float4* rowp = (float4*)(acc_s + tid * 20);
        #pragma unroll
        for (int j = 0; j < 5; j++)
            rowp[j] = make_float4(acc[4 * j], acc[4 * j + 1], acc[4 * j + 2], acc[4 * j + 3]);
    }
    __syncthreads();

    if (tid < 20) {
        float v0 = 0.f, v1 = 0.f, v2 = 0.f, v3 = 0.f;
        #pragma unroll
        for (int i = 0; i < TPB; i += 4) {
            v0 += acc_s[(i + 0) * 20 + tid];
            v1 += acc_s[(i + 1) * 20 + tid];
            v2 += acc_s[(i + 2) * 20 + tid];
            v3 += acc_s[(i + 3) * 20 + tid];
        }
        sums[tid] = (v0 + v1) + (v2 + v3);
    }
    __syncthreads();

    // ---- 4 threads each do one 5-way softmax ----
    if (tid < 4) {
        float sc[W];
        float m = -1e30f;
        #pragma unroll
        for (int w = 0; w < W; w++) {
            sc[w] = sums[tid * W + w];
            m = fmaxf(m, sc[w]);
        }
        float sum = 0.0f;
        #pragma unroll
        for (int w = 0; w < W; w++) {
            sc[w] = expf(sc[w] - m);
            sum += sc[w];
        }
        float inv = 1.0f / sum;
        #pragma unroll
        for (int w = 0; w < W; w++) sh_w[tid * W + w] = sc[w] * inv;
    }
    __syncthreads();

    // ---- Pass 2: weighted sums (rotation form; trig re-read — 10KB/CTA, L1 hits) ----
    float yre[4] = {0, 0, 0, 0};
    float yim[4] = {0, 0, 0, 0};
    float zre[4] = {0, 0, 0, 0};
    float zim[4] = {0, 0, 0, 0};

    #pragma unroll
    for (int w = 0; w < W; w++) {
        const float wa_r = sh_w[0 * W + w];   // LDS broadcasts
        const float wa_i = sh_w[1 * W + w];
        const float wb_r = sh_w[2 * W + w];
        const float wb_i = sh_w[3 * W + w];
        const uint4 tv = gt[rows[w] * (D / 4) + tid];   // same line as pass 1
        const __half2* tp = (const __half2*)&tv;
        #pragma unroll
        for (int k = 0; k < 4; k++) {
            const float2 sc = __half22float2(tp[k]);
            const float s = sc.x, c = sc.y;
            const float hre = fmaf(hrp[k], c, -hip[k] * s);
            const float him = fmaf(hrp[k], s,  hip[k] * c);
            const float tre = fmaf(trp[k], c, -tip[k] * s);
            const float tim = fmaf(trp[k], s,  tip[k] * c);
            yre[k] = fmaf(wa_r, hre, yre[k]);
            yim[k] = fmaf(wa_i, him, yim[k]);
            zre[k] = fmaf(wb_r, tre, zre[k]);
            zim[k] = fmaf(wb_i, tim, zim[k]);
        }
    }

    float local = 0.0f;
    #pragma unroll
    for (int k = 0; k < 4; k++) {
        local += fabsf(yre[k] + rrp[k] - zre[k]);
        local += fabsf(yim[k] + rip[k] + zim[k]);
    }

    local += __shfl_xor_sync(0xffffffffu, local, 16);
    local += __shfl_xor_sync(0xffffffffu, local, 8);
    local += __shfl_xor_sync(0xffffffffu, local, 4);
    local += __shfl_xor_sync(0xffffffffu, local, 2);
    local += __shfl_xor_sync(0xffffffffu, local, 1);
    if (lane == 0) partial[warp] = local;
    __syncthreads();

    if (tid == 0) {
        out[b] = (partial[0] + partial[1]) + (partial[2] + partial[3]);
    }
}

extern "C" void kernel_launch(void* const* d_in, const int* in_sizes, int n_in,
                              void* d_out, int out_size) {
    const int*   h_i = (const int*)  d_in[0];
    const int*   t_i = (const int*)  d_in[1];
    const int*   r_i = (const int*)  d_in[2];
    const int*   d_i = (const int*)  d_in[3];
    const float* eEr = (const float*)d_in[4];
    const float* eEi = (const float*)d_in[5];
    const float* eRr = (const float*)d_in[6];
    const float* eRi = (const float*)d_in[7];
    const float* tt  = (const float*)d_in[8];

    const int B          = in_sizes[0];
    const int time_elems = in_sizes[8];
    const int time_rows  = time_elems / D;
    const int n_day      = time_rows - 2;

    trig_kernel<<<(time_elems + 255) / 256, 256>>>(tt, time_elems);
    contxe_kernel<<<B, TPB>>>(h_i, t_i, r_i, d_i, eEr, eEi, eRr, eRi,
                              (float*)d_out, n_day);
}

// round 17
// speedup vs baseline: 1.7188x; 1.0284x over previous
#include <cuda_runtime.h>
#include <cuda_fp16.h>

#define D      512
#define W      5
#define TPB    128
#define MAX_TIME_ROWS 512

// Precomputed (sin, cos) of the time table as fp16 pairs: g_trig[row*D + dim] = half2(s, c).
// 367*512*4B = 750 KB — L2-resident; 2KB per row -> 10KB per CTA window working set.
__device__ __half2 g_trig[MAX_TIME_ROWS * D];

__global__ void trig_kernel(const float* __restrict__ tt, int n) {
    int i = blockIdx.x * blockDim.x + threadIdx.x;
    if (i < n) {
        float s, c;
        sincosf(tt[i], &s, &c);
        g_trig[i] = __floats2half2_rn(s, c);
    }
}

__global__ __launch_bounds__(TPB, 8) void contxe_kernel(
    const int*   __restrict__ h_i,
    const int*   __restrict__ t_i,
    const int*   __restrict__ r_i,
    const int*   __restrict__ d_i,
    const float* __restrict__ eEr,
    const float* __restrict__ eEi,
    const float* __restrict__ eRr,
    const float* __restrict__ eRi,
    float*       __restrict__ out,
    int n_day)
{
    const int b    = blockIdx.x;
    const int tid  = threadIdx.x;
    const int lane = tid & 31;
    const int warp = tid >> 5;

    __shared__ float acc_s[32 * 20];    // 2.5 KB (32 shuffle-group rows)
    __shared__ float sums[20];
    __shared__ float sh_w[20];
    __shared__ float partial[4];

    const int h = h_i[b];
    const int t = t_i[b];
    const int r = r_i[b];
    const int d = d_i[b];

    // ---- Embedding gathers FIRST (DRAM latency — in flight at cycle 0) ----
    const float4 hr4 = ((const float4*)(eEr + (size_t)h * D))[tid];
    const float4 hi4 = ((const float4*)(eEi + (size_t)h * D))[tid];
    const float4 tr4 = ((const float4*)(eEr + (size_t)t * D))[tid];
    const float4 ti4 = ((const float4*)(eEi + (size_t)t * D))[tid];
    const float4 rr4 = ((const float4*)(eRr + (size_t)r * D))[tid];
    const float4 ri4 = ((const float4*)(eRi + (size_t)r * D))[tid];

    // Window row indices (5 int regs, reused by both passes).
    int rows[W];
    #pragma unroll
    for (int w = 0; w < W; w++) {
        int row = d - (W - 1 - w);
        rows[w] = (row < 0) ? n_day : row;
    }

    const float* hrp = (const float*)&hr4;
    const float* hip = (const float*)&hi4;
    const float* trp = (const float*)&tr4;
    const float* tip = (const float*)&ti4;
    const float* rrp = (const float*)&rr4;
    const float* rip = (const float*)&ri4;

    const uint4* gt = (const uint4*)g_trig;   // 4 half2 (s,c) pairs per uint4; D/4 per row

    // ---- Pass 1: 20 attention-score partial dots (rotation form, trig transient) ----
    float acc[20];
    #pragma unroll
    for (int j = 0; j < 20; j++) acc[j] = 0.0f;

    #pragma unroll
    for (int w = 0; w < W; w++) {
        const uint4 tv = gt[rows[w] * (D / 4) + tid];
        const __half2* tp = (const __half2*)&tv;
        #pragma unroll
        for (int k = 0; k < 4; k++) {
            const float2 sc = __half22float2(tp[k]);
            const float s = sc.x, c = sc.y;
            const float hre = fmaf(hrp[k], c, -hip[k] * s);
            const float him = fmaf(hrp[k], s,  hip[k] * c);
            const float tre = fmaf(trp[k], c, -tip[k] * s);
            const float tim = fmaf(trp[k], s,  tip[k] * c);
            acc[0 * W + w] = fmaf(rrp[k], hre, acc[0 * W + w]);
            acc[1 * W + w] = fmaf(rip[k], him, acc[1 * W + w]);
            acc[2 * W + w] = fmaf(rrp[k], tre, acc[2 * W + w]);
            acc[3 * W + w] = fmaf(rip[k], tim, acc[3 * W + w]);
        }
    }

    // ---- 2-round shuffle pre-reduce (groups of 4 lanes), then 32-row dump ----
    #pragma unroll
    for (int j = 0; j < 20; j++) {
        acc[j] += __shfl_xor_sync(0xffffffffu, acc[j], 1);
        acc[j] += __shfl_xor_sync(0xffffffffu, acc[j], 2);
    }
    if ((tid & 3) == 0) {
        float4* rowp = (float4*)(acc_s + (tid >> 2) * 20);
        #pragma unroll
        for (int j = 0; j < 5; j++)
            rowp[j] = make_float4(acc[4 * j], acc[4 * j + 1], acc[4 * j + 2], acc[4 * j + 3]);
    }
    __syncthreads();

    // ---- Warp 0: 20-thread column sums (32 rows) + 4-thread softmax, one warp ----
    if (warp == 0) {
        if (lane < 20) {
            float v0 = 0.f, v1 = 0.f, v2 = 0.f, v3 = 0.f;
            #pragma unroll
            for (int i = 0; i < 32; i += 4) {
                v0 += acc_s[(i + 0) * 20 + lane];
                v1 += acc_s[(i + 1) * 20 + lane];
                v2 += acc_s[(i + 2) * 20 + lane];
                v3 += acc_s[(i + 3) * 20 + lane];
            }
            sums[lane] = (v0 + v1) + (v2 + v3);
        }
        __syncwarp(0xffffffffu);
        if (lane < 4) {
            float sc[W];
            float m = -1e30f;
            #pragma unroll
            for (int w = 0; w < W; w++) {
                sc[w] = sums[lane * W + w];
                m = fmaxf(m, sc[w]);
            }
            float sum = 0.0f;
            #pragma unroll
            for (int w = 0; w < W; w++) {
                sc[w] = __expf(sc[w] - m);
                sum += sc[w];
            }
            float inv = 1.0f / sum;
            #pragma unroll
            for (int w = 0; w < W; w++) sh_w[lane * W + w] = sc[w] * inv;
        }
    }
    __syncthreads();

    // ---- Pass 2: weighted sums (rotation form; trig re-read — 10KB/CTA, L1 hits) ----
    float yre[4] = {0, 0, 0, 0};
    float yim[4] = {0, 0, 0, 0};
    float zre[4] = {0, 0, 0, 0};
    float zim[4] = {0, 0, 0, 0};

    #pragma unroll
    for (int w = 0; w < W; w++) {
        const float wa_r = sh_w[0 * W + w];   // LDS broadcasts
        const float wa_i = sh_w[1 * W + w];
        const float wb_r = sh_w[2 * W + w];
        const float wb_i = sh_w[3 * W + w];
        const uint4 tv = gt[rows[w] * (D / 4) + tid];   // same line as pass 1
        const __half2* tp = (const __half2*)&tv;
        #pragma unroll
        for (int k = 0; k < 4; k++) {
            const float2 sc = __half22float2(tp[k]);
            const float s = sc.x, c = sc.y;
            const float hre = fmaf(hrp[k], c, -hip[k] * s);
            const float him = fmaf(hrp[k], s,  hip[k] * c);
            const float tre = fmaf(trp[k], c, -tip[k] * s);
            const float tim = fmaf(trp[k], s,  tip[k] * c);
            yre[k] = fmaf(wa_r, hre, yre[k]);
            yim[k] = fmaf(wa_i, him, yim[k]);
            zre[k] = fmaf(wb_r, tre, zre[k]);
            zim[k] = fmaf(wb_i, tim, zim[k]);
        }
    }

    float local = 0.0f;
    #pragma unroll
    for (int k = 0; k < 4; k++) {
        local += fabsf(yre[k] + rrp[k] - zre[k]);
        local += fabsf(yim[k] + rip[k] + zim[k]);
    }

    local += __shfl_xor_sync(0xffffffffu, local, 16);
    local += __shfl_xor_sync(0xffffffffu, local, 8);
    local += __shfl_xor_sync(0xffffffffu, local, 4);
    local += __shfl_xor_sync(0xffffffffu, local, 2);
    local += __shfl_xor_sync(0xffffffffu, local, 1);
    if (lane == 0) partial[warp] = local;
    __syncthreads();

    if (tid == 0) {
        out[b] = (partial[0] + partial[1]) + (partial[2] + partial[3]);
    }
}

extern "C" void kernel_launch(void* const* d_in, const int* in_sizes, int n_in,
                              void* d_out, int out_size) {
    const int*   h_i = (const int*)  d_in[0];
    const int*   t_i = (const int*)  d_in[1];
    const int*   r_i = (const int*)  d_in[2];
    const int*   d_i = (const int*)  d_in[3];
    const float* eEr = (const float*)d_in[4];
    const float* eEi = (const float*)d_in[5];
    const float* eRr = (const float*)d_in[6];
    const float* eRi = (const float*)d_in[7];
    const float* tt  = (const float*)d_in[8];

    const int B          = in_sizes[0];
    const int time_elems = in_sizes[8];
    const int time_rows  = time_elems / D;
    const int n_day      = time_rows - 2;

    trig_kernel<<<(time_elems + 255) / 256, 256>>>(tt, time_elems);
    contxe_kernel<<<B, TPB>>>(h_i, t_i, r_i, d_i, eEr, eEi, eRr, eRi,
                              (float*)d_out, n_day);
}